// round 1
// baseline (speedup 1.0000x reference)
#include <cuda_runtime.h>

// Problem constants
#define VSZ   30000
#define OC    128
#define KW    5
#define BATCH 32

constexpr int L    = 2560;          // 40*64 flattened token positions per batch
constexpr int LOUT = L - KW + 1;    // 2556
constexpr int CW   = VSZ * KW;      // 150000 columns of the K matrix (v*5+w)
constexpr int NSUB = 64;            // sub-chunks of the l-range (one warp each)
constexpr int SUBL = 40;            // 64*40 = 2560 >= LOUT

// Scratch: transposed table Kt[v][w][oc], 16B aligned for float4 gathers (76.8 MB)
__device__ __align__(16) float g_Kt[(size_t)VSZ * KW * OC];
// Per-warp partial maxima: [b][sub][oc-quad]
__device__ float4 g_partial[BATCH][NSUB][OC / 4];

// ---------------------------------------------------------------------------
// Kernel 1: transpose K (128 x 150000, row = oc, col = v*5+w)  ->  Kt[col][row]
// ---------------------------------------------------------------------------
__global__ void transpose_kernel(const float* __restrict__ src) {
    __shared__ float tile[32][33];
    int c  = blockIdx.x * 32 + threadIdx.x;   // column (v*5+w)
    int r0 = blockIdx.y * 32;                 // oc tile base (0,32,64,96)

    #pragma unroll
    for (int i = 0; i < 4; i++) {
        int r = r0 + threadIdx.y + i * 8;     // r < 128 always (grid.y = 4)
        if (c < CW)
            tile[threadIdx.y + i * 8][threadIdx.x] = src[(size_t)r * CW + c];
    }
    __syncthreads();
    #pragma unroll
    for (int i = 0; i < 4; i++) {
        int vw = blockIdx.x * 32 + threadIdx.y + i * 8;
        if (vw < CW)
            g_Kt[(size_t)vw * OC + r0 + threadIdx.x] = tile[threadIdx.x][threadIdx.y + i * 8];
    }
}

// ---------------------------------------------------------------------------
// Kernel 2: gather + sliding-window conv + relu-max
// grid = (NSUB/4, BATCH), block = 128 (4 warps); each warp owns one sub-chunk.
// Lane = oc-quad (float4 over 4 consecutive oc).
// ---------------------------------------------------------------------------
__device__ __forceinline__ void add4(float4& a, const float4 b) {
    a.x += b.x; a.y += b.y; a.z += b.z; a.w += b.w;
}
__device__ __forceinline__ void max4(float4& a, const float4 b) {
    a.x = fmaxf(a.x, b.x); a.y = fmaxf(a.y, b.y);
    a.z = fmaxf(a.z, b.z); a.w = fmaxf(a.w, b.w);
}

__global__ void __launch_bounds__(128) conv_kernel(const int* __restrict__ tokens) {
    const int b    = blockIdx.y;
    const int warp = threadIdx.x >> 5;
    const int lane = threadIdx.x & 31;
    const int sub  = blockIdx.x * 4 + warp;

    const int l0 = sub * SUBL;
    const int l1 = min(l0 + SUBL, LOUT);

    const int* ids = tokens + b * L;
    const float4* __restrict__ Kt4 = reinterpret_cast<const float4*>(g_Kt);

    float4 acc[5];
    #pragma unroll
    for (int i = 0; i < 5; i++) acc[i] = make_float4(0.f, 0.f, 0.f, 0.f);
    float4 vmax = make_float4(0.f, 0.f, 0.f, 0.f);   // relu: floor at 0

    const int pend = l1 + KW - 1;   // tokens p in [l0, pend); pend <= L

    // Unroll by 5 so the ring index (p - l0 - w) mod 5 is compile-time.
    for (int pb = l0; pb < pend; pb += 5) {
        #pragma unroll
        for (int j = 0; j < 5; j++) {
            int p = pb + j;
            if (p < pend) {
                int id = __ldg(ids + p);
                const float4* srcp = Kt4 + (size_t)id * (KW * 32) + lane;
                float4 v0 = __ldg(srcp +   0);
                float4 v1 = __ldg(srcp +  32);
                float4 v2 = __ldg(srcp +  64);
                float4 v3 = __ldg(srcp +  96);
                float4 v4 = __ldg(srcp + 128);
                // conv[l = p - w] += K[:, id, w]; slot(l) = (l - l0) mod 5
                add4(acc[(j + 5 - 0) % 5], v0);
                add4(acc[(j + 5 - 1) % 5], v1);
                add4(acc[(j + 5 - 2) % 5], v2);
                add4(acc[(j + 5 - 3) % 5], v3);
                add4(acc[(j + 5 - 4) % 5], v4);
                // slot (j+1)%5 now holds the completed conv[p-4]
                const int s = (j + 1) % 5;
                if (p >= l0 + 4) max4(vmax, acc[s]);
                acc[s] = make_float4(0.f, 0.f, 0.f, 0.f);
            }
        }
    }
    g_partial[b][sub][lane] = vmax;
}

// ---------------------------------------------------------------------------
// Kernel 3: reduce sub-chunk maxima + tiny FC.  grid = 32 (b), block = 128.
// ---------------------------------------------------------------------------
__global__ void __launch_bounds__(128) final_kernel(const float* __restrict__ fc1_w,
                                                    const float* __restrict__ fc1_b,
                                                    float* __restrict__ out) {
    const int b  = blockIdx.x;
    const int t  = threadIdx.x;          // = oc
    const int warp = t >> 5, lane = t & 31;

    const float* part = reinterpret_cast<const float*>(&g_partial[b][0][0]); // [NSUB][128]
    float pooled = 0.f;
    #pragma unroll 8
    for (int s = 0; s < NSUB; s++)
        pooled = fmaxf(pooled, part[s * OC + t]);

    __shared__ float shw[4][4];          // [warp][tc]
    #pragma unroll
    for (int tc = 0; tc < 4; tc++) {
        float v = pooled * fc1_w[tc * OC + t];
        #pragma unroll
        for (int off = 16; off > 0; off >>= 1)
            v += __shfl_down_sync(0xFFFFFFFFu, v, off);
        if (lane == 0) shw[warp][tc] = v;
    }
    __syncthreads();
    if (t < 4) {
        float s = shw[0][t] + shw[1][t] + shw[2][t] + shw[3][t];
        out[b * 4 + t] = s + fc1_b[t];
    }
}

// ---------------------------------------------------------------------------
extern "C" void kernel_launch(void* const* d_in, const int* in_sizes, int n_in,
                              void* d_out, int out_size) {
    const int*   tokens = (const int*)  d_in[0];
    const float* k1     = (const float*)d_in[1];
    const float* fc1w   = (const float*)d_in[2];
    const float* fc1b   = (const float*)d_in[3];
    float*       out    = (float*)d_out;

    dim3 tgrid((CW + 31) / 32, OC / 32);      // (4688, 4)
    transpose_kernel<<<tgrid, dim3(32, 8)>>>(k1);

    conv_kernel<<<dim3(NSUB / 4, BATCH), 128>>>(tokens);

    final_kernel<<<BATCH, 128>>>(fc1w, fc1b, out);
}

// round 2
// speedup vs baseline: 1.3640x; 1.3640x over previous
#include <cuda_runtime.h>

// Problem constants
#define VSZ   30000
#define OC    128
#define KW    5
#define BATCH 32

constexpr int L    = 2560;          // 40*64 flattened token positions per batch
constexpr int LOUT = L - KW + 1;    // 2556
constexpr int CW   = VSZ * KW;      // 150000 columns of the K matrix (v*5+w)
constexpr int NSUB = 64;            // sub-chunks of the l-range
constexpr int SUBL = 40;            // 64*40 = 2560 >= LOUT

// Scratch: transposed table Kt[v][w][oc], 16B aligned (76.8 MB)
__device__ __align__(16) float g_Kt[(size_t)VSZ * KW * OC];
// Per-warp partial maxima: [b][sub][oc]
__device__ float g_partial[BATCH][NSUB][OC];

// ---------------------------------------------------------------------------
// Kernel 1: transpose K (128 x 150000, row = oc, col = v*5+w)  ->  Kt[col][row]
// Source reads use __ldcs (evict-first) so L2 keeps Kt resident for the conv.
// Each block handles 2 adjacent 32-column tiles to amortize overhead.
// ---------------------------------------------------------------------------
__global__ void transpose_kernel(const float* __restrict__ src) {
    __shared__ float tile[2][32][33];
    const int r0 = blockIdx.y * 32;                 // oc tile base (0,32,64,96)

    #pragma unroll
    for (int t = 0; t < 2; t++) {
        int c = (blockIdx.x * 2 + t) * 32 + threadIdx.x;   // column (v*5+w)
        #pragma unroll
        for (int i = 0; i < 4; i++) {
            int r = r0 + threadIdx.y + i * 8;
            if (c < CW)
                tile[t][threadIdx.y + i * 8][threadIdx.x] =
                    __ldcs(src + (size_t)r * CW + c);
        }
    }
    __syncthreads();
    #pragma unroll
    for (int t = 0; t < 2; t++) {
        #pragma unroll
        for (int i = 0; i < 4; i++) {
            int vw = (blockIdx.x * 2 + t) * 32 + threadIdx.y + i * 8;
            if (vw < CW)
                g_Kt[(size_t)vw * OC + r0 + threadIdx.x] =
                    tile[t][threadIdx.x][threadIdx.y + i * 8];
        }
    }
}

// ---------------------------------------------------------------------------
// Kernel 2: gather + sliding-window conv + relu-max
// grid = (NSUB/4, BATCH), block = 256 (8 warps).
// Each sub-chunk is handled by TWO warps, each covering 64 oc via float2
// lanes -> 4096 warps total (~28/SM) for better MLP, no extra token traffic.
// ---------------------------------------------------------------------------
__device__ __forceinline__ void add2(float2& a, const float2 b) {
    a.x += b.x; a.y += b.y;
}
__device__ __forceinline__ void max2(float2& a, const float2 b) {
    a.x = fmaxf(a.x, b.x); a.y = fmaxf(a.y, b.y);
}

__global__ void __launch_bounds__(256) conv_kernel(const int* __restrict__ tokens) {
    const int b    = blockIdx.y;
    const int warp = threadIdx.x >> 5;
    const int lane = threadIdx.x & 31;
    const int sub  = blockIdx.x * 4 + (warp >> 1);
    const int half = warp & 1;
    const int off  = half * 32 + lane;   // float2 index into the 128-oc row

    const int l0 = sub * SUBL;
    const int l1 = min(l0 + SUBL, LOUT);

    const int* ids = tokens + b * L;
    const float2* __restrict__ Kt2 = reinterpret_cast<const float2*>(g_Kt);

    float2 acc[5];
    #pragma unroll
    for (int i = 0; i < 5; i++) acc[i] = make_float2(0.f, 0.f);
    float2 vmax = make_float2(0.f, 0.f);   // relu: floor at 0

    const int pend = l1 + KW - 1;   // tokens p in [l0, pend); pend <= L

    // Unroll by 5 so the ring index (p - l0 - w) mod 5 is compile-time.
    for (int pb = l0; pb < pend; pb += 5) {
        #pragma unroll
        for (int j = 0; j < 5; j++) {
            int p = pb + j;
            if (p < pend) {
                int id = __ldg(ids + p);
                const float2* srcp = Kt2 + (size_t)id * (KW * 64) + off;
                float2 v0 = __ldg(srcp +   0);
                float2 v1 = __ldg(srcp +  64);
                float2 v2 = __ldg(srcp + 128);
                float2 v3 = __ldg(srcp + 192);
                float2 v4 = __ldg(srcp + 256);
                // conv[l = p - w] += K[:, id, w]; slot(l) = (l - l0) mod 5
                add2(acc[(j + 5 - 0) % 5], v0);
                add2(acc[(j + 5 - 1) % 5], v1);
                add2(acc[(j + 5 - 2) % 5], v2);
                add2(acc[(j + 5 - 3) % 5], v3);
                add2(acc[(j + 5 - 4) % 5], v4);
                // slot (j+1)%5 now holds the completed conv[p-4]
                const int s = (j + 1) % 5;
                if (p >= l0 + 4) max2(vmax, acc[s]);
                acc[s] = make_float2(0.f, 0.f);
            }
        }
    }
    float2* dst = reinterpret_cast<float2*>(&g_partial[b][sub][0]);
    dst[off] = vmax;
}

// ---------------------------------------------------------------------------
// Kernel 3: reduce sub-chunk maxima + tiny FC.  grid = 32 (b), block = 128.
// ---------------------------------------------------------------------------
__global__ void __launch_bounds__(128) final_kernel(const float* __restrict__ fc1_w,
                                                    const float* __restrict__ fc1_b,
                                                    float* __restrict__ out) {
    const int b  = blockIdx.x;
    const int t  = threadIdx.x;          // = oc
    const int warp = t >> 5, lane = t & 31;

    const float* part = &g_partial[b][0][0]; // [NSUB][128]
    float pooled = 0.f;
    #pragma unroll 8
    for (int s = 0; s < NSUB; s++)
        pooled = fmaxf(pooled, part[s * OC + t]);

    __shared__ float shw[4][4];          // [warp][tc]
    #pragma unroll
    for (int tc = 0; tc < 4; tc++) {
        float v = pooled * fc1_w[tc * OC + t];
        #pragma unroll
        for (int off = 16; off > 0; off >>= 1)
            v += __shfl_down_sync(0xFFFFFFFFu, v, off);
        if (lane == 0) shw[warp][tc] = v;
    }
    __syncthreads();
    if (t < 4) {
        float s = shw[0][t] + shw[1][t] + shw[2][t] + shw[3][t];
        out[b * 4 + t] = s + fc1_b[t];
    }
}

// ---------------------------------------------------------------------------
extern "C" void kernel_launch(void* const* d_in, const int* in_sizes, int n_in,
                              void* d_out, int out_size) {
    const int*   tokens = (const int*)  d_in[0];
    const float* k1     = (const float*)d_in[1];
    const float* fc1w   = (const float*)d_in[2];
    const float* fc1b   = (const float*)d_in[3];
    float*       out    = (float*)d_out;

    dim3 tgrid((CW + 63) / 64, OC / 32);      // (2344, 4)
    transpose_kernel<<<tgrid, dim3(32, 8)>>>(k1);

    conv_kernel<<<dim3(NSUB / 4, BATCH), 256>>>(tokens);

    final_kernel<<<BATCH, 128>>>(fc1w, fc1b, out);
}

// round 3
// speedup vs baseline: 1.7982x; 1.3183x over previous
#include <cuda_runtime.h>
#include <cuda_fp16.h>

// Problem constants
#define VSZ   30000
#define OC    128
#define KW    5
#define BATCH 32

constexpr int L    = 2560;          // 40*64 flattened token positions per batch
constexpr int LOUT = L - KW + 1;    // 2556
constexpr int CW   = VSZ * KW;      // 150000 columns of the K matrix (v*5+w)
constexpr int NSUB = 64;            // sub-chunks of the l-range
constexpr int SUBL = 40;            // 64*40 = 2560 >= LOUT

// Scratch: transposed fp16 table Kt[v][w][oc]  (38.4 MB, L2-resident)
__device__ __align__(16) __half g_Kt[(size_t)VSZ * KW * OC];
// Per-warp partial maxima: [b][sub][oc]
__device__ float g_partial[BATCH][NSUB][OC];

// ---------------------------------------------------------------------------
// Kernel 1: transpose + fp32->fp16 convert.
// K is (128 x 150000), row = oc, col = v*5+w.  ->  Kt[col][oc] as half.
// One block = 32 columns x all 128 oc. Write side emits full contiguous
// 256B Kt rows as coalesced uint stores. Source reads __ldcs (evict-first).
// ---------------------------------------------------------------------------
__global__ void __launch_bounds__(256) transpose_kernel(const float* __restrict__ src) {
    __shared__ __half tile[32][130];          // [col-local][oc], 260B row pitch
    const int tx = threadIdx.x & 31;          // column within tile
    const int ty = threadIdx.x >> 5;          // 0..7
    const int c  = blockIdx.x * 32 + tx;      // global column (v*5+w)
    const bool cok = (c < CW);

    #pragma unroll
    for (int i = 0; i < 16; i++) {
        int r = ty + i * 8;                   // oc 0..127
        if (cok)
            tile[tx][r] = __float2half(__ldcs(src + (size_t)r * CW + c));
    }
    __syncthreads();

    // Write out: 32 rows x 64 uints (128 halfs) each = 2048 uints, 8/thread.
    const int colu = threadIdx.x & 63;        // uint index within a Kt row
    const int rbase = threadIdx.x >> 6;       // 0..3
    #pragma unroll
    for (int i = 0; i < 8; i++) {
        int row = rbase + i * 4;              // col-local 0..31
        int vw  = blockIdx.x * 32 + row;
        if (vw < CW) {
            const unsigned* srow = reinterpret_cast<const unsigned*>(&tile[row][0]);
            reinterpret_cast<unsigned*>(g_Kt)[(size_t)vw * 64 + colu] = srow[colu];
        }
    }
}

// ---------------------------------------------------------------------------
// Kernel 2: gather + sliding-window conv + relu-max
// grid = (NSUB/4, BATCH), block = 256 (8 warps).
// Two warps per sub-chunk, each covering 64 oc via half2 lanes; accumulate fp32.
// ---------------------------------------------------------------------------
__device__ __forceinline__ void addh(float2& a, const half2 b) {
    float2 f = __half22float2(b);
    a.x += f.x; a.y += f.y;
}
__device__ __forceinline__ void max2(float2& a, const float2 b) {
    a.x = fmaxf(a.x, b.x); a.y = fmaxf(a.y, b.y);
}

__global__ void __launch_bounds__(256) conv_kernel(const int* __restrict__ tokens) {
    const int b    = blockIdx.y;
    const int warp = threadIdx.x >> 5;
    const int lane = threadIdx.x & 31;
    const int sub  = blockIdx.x * 4 + (warp >> 1);
    const int half = warp & 1;
    const int off  = half * 32 + lane;   // half2 index into the 128-oc row

    const int l0 = sub * SUBL;
    const int l1 = min(l0 + SUBL, LOUT);

    const int* ids = tokens + b * L;
    const half2* __restrict__ Kt2 = reinterpret_cast<const half2*>(g_Kt);

    float2 acc[5];
    #pragma unroll
    for (int i = 0; i < 5; i++) acc[i] = make_float2(0.f, 0.f);
    float2 vmax = make_float2(0.f, 0.f);   // relu: floor at 0

    const int pend = l1 + KW - 1;   // tokens p in [l0, pend); pend <= L

    // Unroll by 5 so the ring index (p - l0 - w) mod 5 is compile-time.
    for (int pb = l0; pb < pend; pb += 5) {
        #pragma unroll
        for (int j = 0; j < 5; j++) {
            int p = pb + j;
            if (p < pend) {
                int id = __ldg(ids + p);
                const half2* srcp = Kt2 + (size_t)id * (KW * 64) + off;
                half2 v0 = __ldg(srcp +   0);
                half2 v1 = __ldg(srcp +  64);
                half2 v2 = __ldg(srcp + 128);
                half2 v3 = __ldg(srcp + 192);
                half2 v4 = __ldg(srcp + 256);
                // conv[l = p - w] += K[:, id, w]; slot(l) = (l - l0) mod 5
                addh(acc[(j + 5 - 0) % 5], v0);
                addh(acc[(j + 5 - 1) % 5], v1);
                addh(acc[(j + 5 - 2) % 5], v2);
                addh(acc[(j + 5 - 3) % 5], v3);
                addh(acc[(j + 5 - 4) % 5], v4);
                // slot (j+1)%5 now holds the completed conv[p-4]
                const int s = (j + 1) % 5;
                if (p >= l0 + 4) max2(vmax, acc[s]);
                acc[s] = make_float2(0.f, 0.f);
            }
        }
    }
    float2* dst = reinterpret_cast<float2*>(&g_partial[b][sub][0]);
    dst[off] = vmax;
}

// ---------------------------------------------------------------------------
// Kernel 3: reduce sub-chunk maxima + tiny FC.  grid = 32 (b), block = 128.
// ---------------------------------------------------------------------------
__global__ void __launch_bounds__(128) final_kernel(const float* __restrict__ fc1_w,
                                                    const float* __restrict__ fc1_b,
                                                    float* __restrict__ out) {
    const int b  = blockIdx.x;
    const int t  = threadIdx.x;          // = oc
    const int warp = t >> 5, lane = t & 31;

    const float* part = &g_partial[b][0][0]; // [NSUB][128]
    float pooled = 0.f;
    #pragma unroll 8
    for (int s = 0; s < NSUB; s++)
        pooled = fmaxf(pooled, part[s * OC + t]);

    __shared__ float shw[4][4];          // [warp][tc]
    #pragma unroll
    for (int tc = 0; tc < 4; tc++) {
        float v = pooled * fc1_w[tc * OC + t];
        #pragma unroll
        for (int off = 16; off > 0; off >>= 1)
            v += __shfl_down_sync(0xFFFFFFFFu, v, off);
        if (lane == 0) shw[warp][tc] = v;
    }
    __syncthreads();
    if (t < 4) {
        float s = shw[0][t] + shw[1][t] + shw[2][t] + shw[3][t];
        out[b * 4 + t] = s + fc1_b[t];
    }
}

// ---------------------------------------------------------------------------
extern "C" void kernel_launch(void* const* d_in, const int* in_sizes, int n_in,
                              void* d_out, int out_size) {
    const int*   tokens = (const int*)  d_in[0];
    const float* k1     = (const float*)d_in[1];
    const float* fc1w   = (const float*)d_in[2];
    const float* fc1b   = (const float*)d_in[3];
    float*       out    = (float*)d_out;

    transpose_kernel<<<(CW + 31) / 32, 256>>>(k1);     // 4688 blocks

    conv_kernel<<<dim3(NSUB / 4, BATCH), 256>>>(tokens);

    final_kernel<<<BATCH, 128>>>(fc1w, fc1b, out);
}